// round 6
// baseline (speedup 1.0000x reference)
#include <cuda_runtime.h>
#include <cstdint>

// Problem constants
#define BB 4
#define SS 8192
#define DD 64
#define NH 8
#define NB 128   // n_buckets

// out elements = B*S*D = 2,097,152 ; buckets elements = B*NH*S = 262,144
#define OUT_ELEMS  (BB * SS * DD)
#define BKT_ELEMS  (BB * NH * SS)

// ---------------------------------------------------------------------------
// out = v  (the reference's masked LSH attention collapses to an exact copy:
// keys are normalized queries, the mask keeps only same-position entries,
// exp(-1e5 - lse) == 0 in fp32, and the hash-round combine weights sum to 1)
// ---------------------------------------------------------------------------
__global__ void copy_v_kernel(const float4* __restrict__ v,
                              float4* __restrict__ out, int n4) {
    int i = blockIdx.x * blockDim.x + threadIdx.x;
    if (i < n4) out[i] = v[i];
}

// ---------------------------------------------------------------------------
// buckets[b, h*S + t] = argmax_i( concat(r, -r) ) + h*NB
//   r[i] = sum_d qk[b,t,d] * rot[d*512 + h*64 + i]     (i in [0,64))
// argmax ties broken by first occurrence (ascending index), like jnp.argmax.
//
// Block: 128 tokens (one b), 256 threads. Each thread owns 4 tokens x 8 i's.
// q is staged transposed in smem; rot slice per h staged in smem.
// ---------------------------------------------------------------------------
__global__ void __launch_bounds__(256)
buckets_kernel(const float* __restrict__ qk,
               const float* __restrict__ rot,
               float* __restrict__ out_b) {
    __shared__ float qT[64 * 128];   // [d][t_local], stride 128 (32 KB)
    __shared__ float rs[64 * 64];    // [d][i] for current h    (16 KB)

    const int g0   = blockIdx.x * 128;          // first global token
    const int tid  = threadIdx.x;
    const int b    = g0 / SS;
    const int tbase = g0 % SS;

    // Stage q transposed (coalesced global reads; smem store conflicts are
    // a one-time ~8K-STS cost, negligible vs compute).
    for (int e = tid; e < 128 * 64; e += 256) {
        int tl = e >> 6, d = e & 63;
        qT[d * 128 + tl] = qk[(size_t)(g0 + tl) * DD + d];
    }

    const int part = tid & 7;    // i-group: i in [part*8, part*8+8)
    const int tg   = tid >> 3;   // t-group: 4 tokens tg*4 .. tg*4+3

    for (int h = 0; h < NH; ++h) {
        __syncthreads();
        // Stage rot[:, h, :] -> rs[d*64 + i] (coalesced)
        for (int e = tid; e < 64 * 64; e += 256) {
            int d = e >> 6, i = e & 63;
            rs[d * 64 + i] = rot[d * (NH * 64) + h * 64 + i];
        }
        __syncthreads();

        float acc[4][8];
        #pragma unroll
        for (int a = 0; a < 4; ++a)
            #pragma unroll
            for (int k = 0; k < 8; ++k) acc[a][k] = 0.f;

        #pragma unroll 4
        for (int d = 0; d < 64; ++d) {
            float4 q4 = *(const float4*)(qT + d * 128 + tg * 4);
            float4 r0 = *(const float4*)(rs + d * 64 + part * 8);
            float4 r1 = *(const float4*)(rs + d * 64 + part * 8 + 4);
            float qv[4] = {q4.x, q4.y, q4.z, q4.w};
            float rv[8] = {r0.x, r0.y, r0.z, r0.w, r1.x, r1.y, r1.z, r1.w};
            #pragma unroll
            for (int a = 0; a < 4; ++a)
                #pragma unroll
                for (int k = 0; k < 8; ++k)
                    acc[a][k] = fmaf(qv[a], rv[k], acc[a][k]);
        }

        const int i0 = part * 8;
        #pragma unroll
        for (int a = 0; a < 4; ++a) {
            // local argmax over [r (idx i0+k), then -r (idx 64+i0+k)];
            // strict '>' gives first-occurrence tie-break in ascending index.
            float bv = acc[a][0]; int bi = i0;
            #pragma unroll
            for (int k = 1; k < 8; ++k)
                if (acc[a][k] > bv) { bv = acc[a][k]; bi = i0 + k; }
            #pragma unroll
            for (int k = 0; k < 8; ++k) {
                float nv = -acc[a][k];
                if (nv > bv) { bv = nv; bi = 64 + i0 + k; }
            }
            // reduce across the 8 parts (consecutive lanes tg*8..tg*8+7)
            #pragma unroll
            for (int off = 4; off >= 1; off >>= 1) {
                float ov = __shfl_down_sync(0xFFFFFFFFu, bv, off);
                int   oi = __shfl_down_sync(0xFFFFFFFFu, bi, off);
                if (ov > bv || (ov == bv && oi < bi)) { bv = ov; bi = oi; }
            }
            if (part == 0) {
                int t = tbase + tg * 4 + a;
                out_b[(size_t)b * (NH * SS) + (size_t)h * SS + t] =
                    (float)(bi + h * NB);
            }
        }
    }
}

extern "C" void kernel_launch(void* const* d_in, const int* in_sizes, int n_in,
                              void* d_out, int out_size) {
    const float* qk  = (const float*)d_in[0];
    const float* v   = (const float*)d_in[1];
    const float* rot = (const float*)d_in[2];
    float* out = (float*)d_out;

    if (out_size >= OUT_ELEMS) {
        // out = v
        int n4 = OUT_ELEMS / 4;
        copy_v_kernel<<<(n4 + 255) / 256, 256>>>(
            (const float4*)v, (float4*)out, n4);
    }
    if (out_size == OUT_ELEMS + BKT_ELEMS) {
        // tuple output: buckets appended (cast to float, values < 1024 exact)
        buckets_kernel<<<(BB * SS) / 128, 256>>>(qk, rot, out + OUT_ELEMS);
    } else if (out_size == BKT_ELEMS) {
        // buckets-only output (defensive)
        buckets_kernel<<<(BB * SS) / 128, 256>>>(qk, rot, out);
    }
}

// round 8
// speedup vs baseline: 1.4511x; 1.4511x over previous
#include <cuda_runtime.h>
#include <cstdint>

// Problem constants
#define BB 4
#define SS 8192
#define DD 64
#define NH 8
#define NB 128   // n_buckets

#define OUT_ELEMS  (BB * SS * DD)   // 2,097,152
#define BKT_ELEMS  (BB * NH * SS)   // 262,144

#define TPB     256   // tokens per block
#define THREADS 256
#define NBLK    ((BB * SS) / TPB)   // 128 blocks
#define QS      260   // qT row stride in floats (mult of 4 for float4, 4-way stage conflicts)

#define SMEM_QT_FLOATS (64 * QS)          // 16640
#define SMEM_RS_FLOATS (64 * 64)          // 4096
#define SMEM_BYTES ((SMEM_QT_FLOATS + SMEM_RS_FLOATS) * 4)   // 82,944 B

__device__ __forceinline__ unsigned long long pack2(float x) {
    unsigned long long r;
    asm("mov.b64 %0, {%1, %1};" : "=l"(r) : "f"(x));
    return r;
}
__device__ __forceinline__ void fma2(unsigned long long& a,
                                     unsigned long long x,
                                     unsigned long long y) {
    // packed fp32x2 FMA (Blackwell): 2 FMAs per lane per instruction
    asm("fma.rn.f32x2 %0, %1, %2, %0;" : "+l"(a) : "l"(x), "l"(y));
}
__device__ __forceinline__ float lo32(unsigned long long a) {
    return __uint_as_float((unsigned)(a & 0xffffffffull));
}
__device__ __forceinline__ float hi32(unsigned long long a) {
    return __uint_as_float((unsigned)(a >> 32));
}

// ---------------------------------------------------------------------------
// Fused kernel:
//   (a) out[0:OUT] = v              (the masked LSH attention collapses to v)
//   (b) out_b[b, h*S + t] = argmax_i concat(r, -r) + h*NB,
//       r[i] = sum_d qk[b,t,d] * rot[d, h, i]
//
// Block = 256 tokens. 256 threads: tg = tid>>3 owns 8 tokens, part = tid&7
// owns 8 i's. Inner product over d uses fp32x2 FMA with accumulators paired
// over adjacent tokens (contiguous in transposed qT -> pairs load for free);
// r values duplicated into both lanes via mov.b64 (ALU pipe, non-binding).
// ---------------------------------------------------------------------------
__global__ void __launch_bounds__(THREADS, 1)
lsh_fused_kernel(const float* __restrict__ qk,
                 const float* __restrict__ rot,
                 const float* __restrict__ v,
                 float* __restrict__ out,
                 float* __restrict__ out_b,
                 int do_copy, int do_bkt) {
    extern __shared__ float sm[];
    float* qT = sm;                    // [d][t_local], stride QS
    float* rs = sm + SMEM_QT_FLOATS;   // [d][i], stride 64

    const int tid   = threadIdx.x;
    const int g0    = blockIdx.x * TPB;
    const int b     = g0 / SS;
    const int tbase = g0 % SS;

    // (a) copy this block's v slice (DRAM traffic hides under FMA compute)
    if (do_copy) {
        const float4* vs = (const float4*)v + (size_t)g0 * (DD / 4);
        float4*       os = (float4*)out    + (size_t)g0 * (DD / 4);
        #pragma unroll 4
        for (int e = tid; e < TPB * DD / 4; e += THREADS) os[e] = vs[e];
    }
    if (!do_bkt) return;

    // stage q transposed (coalesced global reads; 4-way smem store conflicts)
    for (int e = tid; e < TPB * 64; e += THREADS) {
        int tl = e >> 6, d = e & 63;
        qT[d * QS + tl] = qk[(size_t)(g0 + tl) * DD + d];
    }

    const int part = tid & 7;    // i in [part*8, part*8+8)
    const int tg   = tid >> 3;   // tokens tg*8 .. tg*8+7
    const float* qp = qT + tg * 8;
    const float* rp = rs + part * 8;
    const int i0 = part * 8;

    for (int h = 0; h < NH; ++h) {
        __syncthreads();   // also covers qT readiness on h==0
        // stage rot[:, h, :] -> rs (coalesced both sides)
        for (int e = tid; e < 64 * 64; e += THREADS) {
            int d = e >> 6, i = e & 63;
            rs[d * 64 + i] = rot[d * (NH * 64) + h * 64 + i];
        }
        __syncthreads();

        unsigned long long acc[4][8];   // [token-pair][i]; 0ull == (0.f, 0.f)
        #pragma unroll
        for (int p = 0; p < 4; ++p)
            #pragma unroll
            for (int k = 0; k < 8; ++k) acc[p][k] = 0ull;

        #pragma unroll 4
        for (int d = 0; d < 64; ++d) {
            // q: 8 tokens = 4 natural pairs (tokens contiguous in qT rows)
            ulonglong2 qA = *(const ulonglong2*)(qp + d * QS);
            ulonglong2 qB = *(const ulonglong2*)(qp + d * QS + 4);
            float4 r0 = *(const float4*)(rp + d * 64);
            float4 r1 = *(const float4*)(rp + d * 64 + 4);
            unsigned long long qq[4] = {qA.x, qA.y, qB.x, qB.y};
            unsigned long long rr[8] = {
                pack2(r0.x), pack2(r0.y), pack2(r0.z), pack2(r0.w),
                pack2(r1.x), pack2(r1.y), pack2(r1.z), pack2(r1.w)};
            #pragma unroll
            for (int p = 0; p < 4; ++p)
                #pragma unroll
                for (int k = 0; k < 8; ++k)
                    fma2(acc[p][k], qq[p], rr[k]);
        }

        // epilogue: per-token argmax over [r, -r], then reduce across 8 parts
        #pragma unroll
        for (int p = 0; p < 4; ++p) {
            #pragma unroll
            for (int half = 0; half < 2; ++half) {
                float vv[8];
                #pragma unroll
                for (int k = 0; k < 8; ++k)
                    vv[k] = half ? hi32(acc[p][k]) : lo32(acc[p][k]);

                // strict '>' => first-occurrence tie-break (ascending index)
                float bv = vv[0]; int bi = i0;
                #pragma unroll
                for (int k = 1; k < 8; ++k)
                    if (vv[k] > bv) { bv = vv[k]; bi = i0 + k; }
                #pragma unroll
                for (int k = 0; k < 8; ++k) {
                    float nv = -vv[k];
                    if (nv > bv) { bv = nv; bi = 64 + i0 + k; }
                }
                // reduce across the 8 parts (consecutive lanes)
                #pragma unroll
                for (int off = 4; off >= 1; off >>= 1) {
                    float ov = __shfl_down_sync(0xFFFFFFFFu, bv, off);
                    int   oi = __shfl_down_sync(0xFFFFFFFFu, bi, off);
                    if (ov > bv || (ov == bv && oi < bi)) { bv = ov; bi = oi; }
                }
                if (part == 0) {
                    int t = tbase + tg * 8 + p * 2 + half;
                    out_b[(size_t)b * (NH * SS) + (size_t)h * SS + t] =
                        (float)(bi + h * NB);
                }
            }
        }
    }
}

extern "C" void kernel_launch(void* const* d_in, const int* in_sizes, int n_in,
                              void* d_out, int out_size) {
    const float* qk  = (const float*)d_in[0];
    const float* v   = (const float*)d_in[1];
    const float* rot = (const float*)d_in[2];
    float* out = (float*)d_out;

    // opt in to >48KB dynamic smem (sticky per function; first call is
    // outside graph capture, so the attribute persists for captured replays)
    cudaFuncSetAttribute(lsh_fused_kernel,
                         cudaFuncAttributeMaxDynamicSharedMemorySize,
                         SMEM_BYTES);

    int do_copy = (out_size >= OUT_ELEMS) ? 1 : 0;
    int do_bkt  = (out_size == OUT_ELEMS + BKT_ELEMS || out_size == BKT_ELEMS) ? 1 : 0;
    float* out_b = (out_size == BKT_ELEMS) ? out : out + OUT_ELEMS;

    lsh_fused_kernel<<<NBLK, THREADS, SMEM_BYTES>>>(
        qk, rot, v, out, out_b, do_copy, do_bkt);
}